// round 4
// baseline (speedup 1.0000x reference)
#include <cuda_runtime.h>
#include <cstddef>

// Problem constants (H = V = O = 4096, M = 104, DM = 1)
#define H 4096
#define M_STACK 104

// Scratch for the hidden vector h between the two kernels.
__device__ float g_h[H];

// ---------------------------------------------------------------------------
// Kernel 1: h = tanh(W_ih @ emb + b_ih + W_hh @ hbar + b_hh)
//   emb  = E[idx, :]
//   hbar = W_sh[:,0]*stack[0] + b_sh + hidden0
// Grid 1024 x 256 threads. 4 rows per block; each row gets TWO warps:
//   warp (2r+0) -> W_ih row . emb
//   warp (2r+1) -> W_hh row . hbar
// -> 8192 warps total (2x round-1) for latency hiding.
// ---------------------------------------------------------------------------
__global__ __launch_bounds__(256, 6) void srnn_hidden_kernel(
    const int* __restrict__ inp,
    const float* __restrict__ hidden0,
    const float* __restrict__ stack,
    const float* __restrict__ E,
    const float* __restrict__ W_ih,
    const float* __restrict__ b_ih,
    const float* __restrict__ W_hh,
    const float* __restrict__ b_hh,
    const float* __restrict__ W_sh,
    const float* __restrict__ b_sh,
    float* __restrict__ out_hidden)   // d_out + H
{
    __shared__ float4 s_emb4[H / 4];
    __shared__ float4 s_hbar4[H / 4];
    __shared__ float  s_part[8];

    const int tid = threadIdx.x;
    const int idx = inp[0];
    const float s0 = stack[0];

    const float4* __restrict__ E4   = (const float4*)(E + (size_t)idx * H);
    const float4* __restrict__ h04  = (const float4*)hidden0;
    const float4* __restrict__ bsh4 = (const float4*)b_sh;
    const float4* __restrict__ wsh4 = (const float4*)W_sh;

#pragma unroll
    for (int k = 0; k < 4; ++k) {
        const int v = tid + k * 256;           // float4 index 0..1023
        s_emb4[v] = E4[v];
        const float4 a = h04[v];
        const float4 b = bsh4[v];
        const float4 w = wsh4[v];
        float4 hb;
        hb.x = fmaf(w.x, s0, a.x + b.x);
        hb.y = fmaf(w.y, s0, a.y + b.y);
        hb.z = fmaf(w.z, s0, a.z + b.z);
        hb.w = fmaf(w.w, s0, a.w + b.w);
        s_hbar4[v] = hb;
    }
    __syncthreads();

    const int warp = tid >> 5;
    const int lane = tid & 31;
    const int row  = blockIdx.x * 4 + (warp >> 1);
    const int mat  = warp & 1;

    const float4* __restrict__ A4 =
        (const float4*)((mat ? W_hh : W_ih) + (size_t)row * H);
    const float4* __restrict__ X4 = mat ? s_hbar4 : s_emb4;

    float acc = 0.0f;
#pragma unroll 8
    for (int k = 0; k < 32; ++k) {
        const int v = lane + k * 32;
        const float4 a = A4[v];
        const float4 x = X4[v];
        acc += a.x * x.x + a.y * x.y + a.z * x.z + a.w * x.w;
    }
#pragma unroll
    for (int off = 16; off > 0; off >>= 1)
        acc += __shfl_xor_sync(0xFFFFFFFFu, acc, off);
    if (lane == 0) s_part[warp] = acc;
    __syncthreads();

    if (tid < 4) {
        const int r = blockIdx.x * 4 + tid;
        const float h = tanhf(s_part[2 * tid] + s_part[2 * tid + 1]
                              + b_ih[r] + b_hh[r]);
        g_h[r] = h;
        out_hidden[r] = h;   // "hidden" output slice
    }
}

// ---------------------------------------------------------------------------
// Kernel 2:
//   blocks 0..1023 : output = sigmoid(W_y @ h + b_y)
//     4 rows/block; each row handled by TWO warps, each over half of K.
//   block 1024     : softmax(W_a@h+b_a), sigmoid(W_n@h+b_n), stack blend.
// ---------------------------------------------------------------------------
__global__ __launch_bounds__(256, 6) void srnn_output_kernel(
    const float* __restrict__ W_y,
    const float* __restrict__ b_y,
    const float* __restrict__ W_n,
    const float* __restrict__ b_n,
    const float* __restrict__ W_a,
    const float* __restrict__ b_a,
    const float* __restrict__ stack,
    float* __restrict__ d_out)
{
    const int tid  = threadIdx.x;
    const int warp = tid >> 5;
    const int lane = tid & 31;

    if (blockIdx.x < 1024) {
        __shared__ float4 s_h4[H / 4];
        __shared__ float  s_part[8];
        const float4* gh4 = (const float4*)g_h;
#pragma unroll
        for (int k = 0; k < 4; ++k) {
            const int v = tid + k * 256;
            s_h4[v] = gh4[v];
        }
        __syncthreads();

        const int row  = blockIdx.x * 4 + (warp >> 1);
        const int half = warp & 1;
        const int base = half * (H / 8);    // float4 index offset (512)
        const float4* __restrict__ A4 = (const float4*)(W_y + (size_t)row * H);

        float acc = 0.0f;
#pragma unroll 8
        for (int k = 0; k < 16; ++k) {
            const int v = base + lane + k * 32;
            const float4 a = A4[v];
            const float4 x = s_h4[v];
            acc += a.x * x.x + a.y * x.y + a.z * x.z + a.w * x.w;
        }
#pragma unroll
        for (int off = 16; off > 0; off >>= 1)
            acc += __shfl_xor_sync(0xFFFFFFFFu, acc, off);
        if (lane == 0) s_part[warp] = acc;
        __syncthreads();

        if (tid < 4) {
            const int r = blockIdx.x * 4 + tid;
            const float z = s_part[2 * tid] + s_part[2 * tid + 1] + b_y[r];
            d_out[r] = 1.0f / (1.0f + expf(-z));   // "output" slice
        }
    } else {
        // Tiny tail block: 3 dot products over h, softmax, stack blend.
        __shared__ float s_dots[3];
        __shared__ float s_aw0, s_aw1, s_ne;

        if (warp < 3) {
            const float* __restrict__ Wrow =
                (warp < 2) ? (W_a + (size_t)warp * H) : W_n;
            const float4* __restrict__ A4 = (const float4*)Wrow;
            const float4* __restrict__ h4 = (const float4*)g_h;
            float acc = 0.0f;
#pragma unroll 8
            for (int k = 0; k < 32; ++k) {
                const int v = lane + k * 32;
                const float4 a = A4[v];
                const float4 x = h4[v];
                acc += a.x * x.x + a.y * x.y + a.z * x.z + a.w * x.w;
            }
#pragma unroll
            for (int off = 16; off > 0; off >>= 1)
                acc += __shfl_xor_sync(0xFFFFFFFFu, acc, off);
            if (lane == 0) s_dots[warp] = acc;
        }
        __syncthreads();

        if (tid == 0) {
            const float a0 = s_dots[0] + b_a[0];
            const float a1 = s_dots[1] + b_a[1];
            const float m  = fmaxf(a0, a1);
            const float e0 = expf(a0 - m);
            const float e1 = expf(a1 - m);
            const float inv = 1.0f / (e0 + e1);
            const float aw0 = e0 * inv;
            const float aw1 = e1 * inv;
            s_aw0 = aw0;
            s_aw1 = aw1;
            s_ne  = 1.0f / (1.0f + expf(-(s_dots[2] + b_n[0])));
            d_out[2 * H + M_STACK] = aw0 + aw1;       // "weights" scalar
        }
        __syncthreads();

        if (tid < M_STACK) {
            const float push = (tid == 0) ? s_ne : stack[tid - 1];
            const float pop  = (tid < M_STACK - 1) ? stack[tid + 1] : 0.0f;
            d_out[2 * H + tid] = s_aw0 * push + s_aw1 * pop;  // "new_stack"
        }
    }
}

// ---------------------------------------------------------------------------
// Launch
// Inputs (metadata order): 0 inp(int), 1 hidden0, 2 stack, 3 E, 4 W_ih,
// 5 b_ih, 6 W_hh, 7 b_hh, 8 W_y, 9 b_y, 10 W_n, 11 b_n, 12 W_a, 13 b_a,
// 14 W_sh, 15 b_sh.
// Output layout: [output 4096 | hidden 4096 | new_stack 104 | weights 1]
// ---------------------------------------------------------------------------
extern "C" void kernel_launch(void* const* d_in, const int* in_sizes, int n_in,
                              void* d_out, int out_size)
{
    (void)in_sizes; (void)n_in; (void)out_size;

    const int*   inp     = (const int*)  d_in[0];
    const float* hidden0 = (const float*)d_in[1];
    const float* stack   = (const float*)d_in[2];
    const float* E       = (const float*)d_in[3];
    const float* W_ih    = (const float*)d_in[4];
    const float* b_ih    = (const float*)d_in[5];
    const float* W_hh    = (const float*)d_in[6];
    const float* b_hh    = (const float*)d_in[7];
    const float* W_y     = (const float*)d_in[8];
    const float* b_y     = (const float*)d_in[9];
    const float* W_n     = (const float*)d_in[10];
    const float* b_n     = (const float*)d_in[11];
    const float* W_a     = (const float*)d_in[12];
    const float* b_a     = (const float*)d_in[13];
    const float* W_sh    = (const float*)d_in[14];
    const float* b_sh    = (const float*)d_in[15];

    float* out = (float*)d_out;

    srnn_hidden_kernel<<<1024, 256>>>(inp, hidden0, stack, E, W_ih, b_ih,
                                      W_hh, b_hh, W_sh, b_sh, out + H);
    srnn_output_kernel<<<1025, 256>>>(W_y, b_y, W_n, b_n, W_a, b_a,
                                      stack, out);
}

// round 5
// speedup vs baseline: 1.0793x; 1.0793x over previous
#include <cuda_runtime.h>
#include <cstddef>

// Problem constants (H = V = O = 4096, M = 104, DM = 1)
#define H 4096
#define M_STACK 104

// Scratch between kernels.
__device__ float g_h[H];     // hidden vector h
__device__ float g_hbar[H];  // hbar = W_sh[:,0]*stack[0] + b_sh + hidden0

// ---------------------------------------------------------------------------
// Kernel 0: g_hbar = W_sh[:,0]*stack[0] + b_sh + hidden0   (tiny)
// ---------------------------------------------------------------------------
__global__ __launch_bounds__(128) void srnn_hbar_kernel(
    const float* __restrict__ hidden0,
    const float* __restrict__ stack,
    const float* __restrict__ W_sh,
    const float* __restrict__ b_sh)
{
    const int i = blockIdx.x * 128 + threadIdx.x;   // grid 32 x 128 = 4096
    const float s0 = stack[0];
    g_hbar[i] = fmaf(W_sh[i], s0, b_sh[i] + hidden0[i]);
}

// ---------------------------------------------------------------------------
// Kernel 1: h = tanh(W_ih @ emb + b_ih + W_hh @ hbar + b_hh)
// Grid 1024 x 128 threads (4 warps). One warp per row, streaming BOTH
// matrix rows (2 independent global streams, 16 LDG.128 per unroll window).
// 7 blocks/SM resident (smem 32KB) -> one wave, ~99% balanced.
// ---------------------------------------------------------------------------
__global__ __launch_bounds__(128, 7) void srnn_hidden_kernel(
    const int* __restrict__ inp,
    const float* __restrict__ E,
    const float* __restrict__ W_ih,
    const float* __restrict__ b_ih,
    const float* __restrict__ W_hh,
    const float* __restrict__ b_hh,
    float* __restrict__ out_hidden)   // d_out + H
{
    __shared__ float4 s_emb4[H / 4];
    __shared__ float4 s_hbar4[H / 4];
    __shared__ float  s_part[4];

    const int tid = threadIdx.x;
    const int idx = inp[0];

    const float4* __restrict__ E4  = (const float4*)(E + (size_t)idx * H);
    const float4* __restrict__ hb4 = (const float4*)g_hbar;

#pragma unroll
    for (int k = 0; k < 8; ++k) {
        const int v = tid + k * 128;           // float4 index 0..1023
        s_emb4[v]  = E4[v];
        s_hbar4[v] = hb4[v];
    }
    __syncthreads();

    const int warp = tid >> 5;
    const int lane = tid & 31;
    const int row  = blockIdx.x * 4 + warp;

    const float4* __restrict__ A4 = (const float4*)(W_ih + (size_t)row * H);
    const float4* __restrict__ B4 = (const float4*)(W_hh + (size_t)row * H);

    float acc0 = 0.0f, acc1 = 0.0f;
#pragma unroll 8
    for (int k = 0; k < 32; ++k) {
        const int v = lane + k * 32;
        const float4 a = A4[v];
        const float4 x = s_emb4[v];
        acc0 += a.x * x.x + a.y * x.y + a.z * x.z + a.w * x.w;
        const float4 b = B4[v];
        const float4 y = s_hbar4[v];
        acc1 += b.x * y.x + b.y * y.y + b.z * y.z + b.w * y.w;
    }
    float acc = acc0 + acc1;
#pragma unroll
    for (int off = 16; off > 0; off >>= 1)
        acc += __shfl_xor_sync(0xFFFFFFFFu, acc, off);
    if (lane == 0) s_part[warp] = acc;
    __syncthreads();

    if (tid < 4) {
        const int r = blockIdx.x * 4 + tid;
        const float h = tanhf(s_part[tid] + b_ih[r] + b_hh[r]);
        g_h[r] = h;
        out_hidden[r] = h;   // "hidden" output slice
    }
}

// ---------------------------------------------------------------------------
// Kernel 2:
//   blocks 0..1023 : output = sigmoid(W_y @ h + b_y)
//     4 rows/block; one warp per row, TWO streams (row halves), dual accs.
//     64 regs (launch_bounds 128,8) -> deep LDG batching; 7-8 blocks/SM,
//     one wave.
//   block 1024     : softmax(W_a@h+b_a), sigmoid(W_n@h+b_n), stack blend.
// ---------------------------------------------------------------------------
__global__ __launch_bounds__(128, 8) void srnn_output_kernel(
    const float* __restrict__ W_y,
    const float* __restrict__ b_y,
    const float* __restrict__ W_n,
    const float* __restrict__ b_n,
    const float* __restrict__ W_a,
    const float* __restrict__ b_a,
    const float* __restrict__ stack,
    float* __restrict__ d_out)
{
    const int tid  = threadIdx.x;
    const int warp = tid >> 5;
    const int lane = tid & 31;

    if (blockIdx.x < 1024) {
        __shared__ float4 s_h4[H / 4];
        __shared__ float  s_part[4];
        const float4* gh4 = (const float4*)g_h;
#pragma unroll
        for (int k = 0; k < 8; ++k) {
            const int v = tid + k * 128;
            s_h4[v] = gh4[v];
        }
        __syncthreads();

        const int row = blockIdx.x * 4 + warp;
        const float4* __restrict__ A4 = (const float4*)(W_y + (size_t)row * H);

        float acc0 = 0.0f, acc1 = 0.0f;
#pragma unroll 8
        for (int k = 0; k < 16; ++k) {
            const int v0 = lane + k * 32;        // first half  (0..511)
            const int v1 = v0 + 512;             // second half (512..1023)
            const float4 a0 = A4[v0];
            const float4 x0 = s_h4[v0];
            acc0 += a0.x * x0.x + a0.y * x0.y + a0.z * x0.z + a0.w * x0.w;
            const float4 a1 = A4[v1];
            const float4 x1 = s_h4[v1];
            acc1 += a1.x * x1.x + a1.y * x1.y + a1.z * x1.z + a1.w * x1.w;
        }
        float acc = acc0 + acc1;
#pragma unroll
        for (int off = 16; off > 0; off >>= 1)
            acc += __shfl_xor_sync(0xFFFFFFFFu, acc, off);
        if (lane == 0) s_part[warp] = acc;
        __syncthreads();

        if (tid < 4) {
            const int r = blockIdx.x * 4 + tid;
            const float z = s_part[tid] + b_y[r];
            d_out[r] = 1.0f / (1.0f + expf(-z));   // "output" slice
        }
    } else {
        // Tiny tail block: 3 dot products over h, softmax, stack blend.
        __shared__ float s_dots[3];
        __shared__ float s_aw0, s_aw1, s_ne;

        if (warp < 3) {
            const float* __restrict__ Wrow =
                (warp < 2) ? (W_a + (size_t)warp * H) : W_n;
            const float4* __restrict__ A4 = (const float4*)Wrow;
            const float4* __restrict__ h4 = (const float4*)g_h;
            float acc = 0.0f;
#pragma unroll 8
            for (int k = 0; k < 32; ++k) {
                const int v = lane + k * 32;
                const float4 a = A4[v];
                const float4 x = h4[v];
                acc += a.x * x.x + a.y * x.y + a.z * x.z + a.w * x.w;
            }
#pragma unroll
            for (int off = 16; off > 0; off >>= 1)
                acc += __shfl_xor_sync(0xFFFFFFFFu, acc, off);
            if (lane == 0) s_dots[warp] = acc;
        }
        __syncthreads();

        if (tid == 0) {
            const float a0 = s_dots[0] + b_a[0];
            const float a1 = s_dots[1] + b_a[1];
            const float m  = fmaxf(a0, a1);
            const float e0 = expf(a0 - m);
            const float e1 = expf(a1 - m);
            const float inv = 1.0f / (e0 + e1);
            const float aw0 = e0 * inv;
            const float aw1 = e1 * inv;
            s_aw0 = aw0;
            s_aw1 = aw1;
            s_ne  = 1.0f / (1.0f + expf(-(s_dots[2] + b_n[0])));
            d_out[2 * H + M_STACK] = aw0 + aw1;       // "weights" scalar
        }
        __syncthreads();

        if (tid < M_STACK) {
            const float push = (tid == 0) ? s_ne : stack[tid - 1];
            const float pop  = (tid < M_STACK - 1) ? stack[tid + 1] : 0.0f;
            d_out[2 * H + tid] = s_aw0 * push + s_aw1 * pop;  // "new_stack"
        }
    }
}

// ---------------------------------------------------------------------------
// Launch
// Inputs (metadata order): 0 inp(int), 1 hidden0, 2 stack, 3 E, 4 W_ih,
// 5 b_ih, 6 W_hh, 7 b_hh, 8 W_y, 9 b_y, 10 W_n, 11 b_n, 12 W_a, 13 b_a,
// 14 W_sh, 15 b_sh.
// Output layout: [output 4096 | hidden 4096 | new_stack 104 | weights 1]
// ---------------------------------------------------------------------------
extern "C" void kernel_launch(void* const* d_in, const int* in_sizes, int n_in,
                              void* d_out, int out_size)
{
    (void)in_sizes; (void)n_in; (void)out_size;

    const int*   inp     = (const int*)  d_in[0];
    const float* hidden0 = (const float*)d_in[1];
    const float* stack   = (const float*)d_in[2];
    const float* E       = (const float*)d_in[3];
    const float* W_ih    = (const float*)d_in[4];
    const float* b_ih    = (const float*)d_in[5];
    const float* W_hh    = (const float*)d_in[6];
    const float* b_hh    = (const float*)d_in[7];
    const float* W_y     = (const float*)d_in[8];
    const float* b_y     = (const float*)d_in[9];
    const float* W_n     = (const float*)d_in[10];
    const float* b_n     = (const float*)d_in[11];
    const float* W_a     = (const float*)d_in[12];
    const float* b_a     = (const float*)d_in[13];
    const float* W_sh    = (const float*)d_in[14];
    const float* b_sh    = (const float*)d_in[15];

    float* out = (float*)d_out;

    srnn_hbar_kernel<<<32, 128>>>(hidden0, stack, W_sh, b_sh);
    srnn_hidden_kernel<<<1024, 128>>>(inp, E, W_ih, b_ih, W_hh, b_hh,
                                      out + H);
    srnn_output_kernel<<<1025, 128>>>(W_y, b_y, W_n, b_n, W_a, b_a,
                                      stack, out);
}

// round 8
// speedup vs baseline: 1.2273x; 1.1371x over previous
#include <cuda_runtime.h>
#include <cstddef>

// Problem constants (H = V = O = 4096, M = 104, DM = 1)
#define H 4096
#define M_STACK 104

// Scratch for the hidden vector h between the two kernels.
__device__ float g_h[H];

// ---------------------------------------------------------------------------
// Kernel 1: h = tanh(W_ih @ emb + b_ih + W_hh @ hbar + b_hh)
//   emb  = E[idx, :]
//   hbar = W_sh[:,0]*stack[0] + b_sh + hidden0
// 512 blocks x 256 threads; block stages emb+hbar in smem, then one warp
// per row streaming BOTH matrices (2 independent LDG streams/warp).
// This exact structure measured ~5.4 TB/s in round 1.
// ---------------------------------------------------------------------------
__global__ __launch_bounds__(256) void srnn_hidden_kernel(
    const int* __restrict__ inp,
    const float* __restrict__ hidden0,
    const float* __restrict__ stack,
    const float* __restrict__ E,
    const float* __restrict__ W_ih,
    const float* __restrict__ b_ih,
    const float* __restrict__ W_hh,
    const float* __restrict__ b_hh,
    const float* __restrict__ W_sh,
    const float* __restrict__ b_sh,
    float* __restrict__ out_hidden)   // d_out + H
{
    __shared__ float4 s_emb4[H / 4];
    __shared__ float4 s_hbar4[H / 4];
    __shared__ float  s_part[8];

    const int tid = threadIdx.x;
    const int idx = inp[0];
    const float s0 = stack[0];

    const float4* __restrict__ E4   = (const float4*)(E + (size_t)idx * H);
    const float4* __restrict__ h04  = (const float4*)hidden0;
    const float4* __restrict__ bsh4 = (const float4*)b_sh;
    const float4* __restrict__ wsh4 = (const float4*)W_sh;

#pragma unroll
    for (int k = 0; k < 4; ++k) {
        const int v = tid + k * 256;           // float4 index 0..1023
        s_emb4[v] = E4[v];
        const float4 a = h04[v];
        const float4 b = bsh4[v];
        const float4 w = wsh4[v];
        float4 hb;
        hb.x = fmaf(w.x, s0, a.x + b.x);
        hb.y = fmaf(w.y, s0, a.y + b.y);
        hb.z = fmaf(w.z, s0, a.z + b.z);
        hb.w = fmaf(w.w, s0, a.w + b.w);
        s_hbar4[v] = hb;
    }
    __syncthreads();

    const int warp = tid >> 5;
    const int lane = tid & 31;
    const int row  = blockIdx.x * 8 + warp;

    const float4* __restrict__ A4 = (const float4*)(W_ih + (size_t)row * H);
    const float4* __restrict__ B4 = (const float4*)(W_hh + (size_t)row * H);

    float acc0 = 0.0f, acc1 = 0.0f;
#pragma unroll 8
    for (int k = 0; k < 32; ++k) {
        const int v = lane + k * 32;
        const float4 a = A4[v];
        const float4 x = s_emb4[v];
        acc0 += a.x * x.x + a.y * x.y + a.z * x.z + a.w * x.w;
        const float4 b = B4[v];
        const float4 y = s_hbar4[v];
        acc1 += b.x * y.x + b.y * y.y + b.z * y.z + b.w * y.w;
    }
    float acc = acc0 + acc1;
#pragma unroll
    for (int off = 16; off > 0; off >>= 1)
        acc += __shfl_xor_sync(0xFFFFFFFFu, acc, off);
    if (lane == 0) s_part[warp] = acc;
    __syncthreads();

    if (tid < 8) {
        const int r = blockIdx.x * 8 + tid;
        const float h = tanhf(s_part[tid] + b_ih[r] + b_hh[r]);
        g_h[r] = h;
        out_hidden[r] = h;   // "hidden" output slice
    }
}

// ---------------------------------------------------------------------------
// Kernel 2:
//   blocks 0..511 : output = sigmoid(W_y @ h + b_y)
//     8 rows/block; each warp handles TWO rows over HALF of K
//     -> 2 independent LDG streams per warp (the round-1 BW lever).
//   block 512     : softmax(W_a@h+b_a), sigmoid(W_n@h+b_n), stack blend.
// ---------------------------------------------------------------------------
__global__ __launch_bounds__(256) void srnn_output_kernel(
    const float* __restrict__ W_y,
    const float* __restrict__ b_y,
    const float* __restrict__ W_n,
    const float* __restrict__ b_n,
    const float* __restrict__ W_a,
    const float* __restrict__ b_a,
    const float* __restrict__ stack,
    float* __restrict__ d_out)
{
    const int tid  = threadIdx.x;
    const int warp = tid >> 5;
    const int lane = tid & 31;

    if (blockIdx.x < 512) {
        __shared__ float4 s_h4[H / 4];
        __shared__ float  s_part[16];
        const float4* gh4 = (const float4*)g_h;
#pragma unroll
        for (int k = 0; k < 4; ++k) {
            const int v = tid + k * 256;
            s_h4[v] = gh4[v];
        }
        __syncthreads();

        const int pr   = warp & 3;              // row pair 0..3
        const int hf   = warp >> 2;             // K half 0/1
        const int r0   = blockIdx.x * 8 + pr * 2;
        const int base = hf * 512;              // float4 offset
        const float4* __restrict__ A0 = (const float4*)(W_y + (size_t)r0 * H);
        const float4* __restrict__ A1 = (const float4*)(W_y + (size_t)(r0 + 1) * H);

        float acc0 = 0.0f, acc1 = 0.0f;
#pragma unroll 8
        for (int k = 0; k < 16; ++k) {
            const int v = base + lane + k * 32;
            const float4 x  = s_h4[v];
            const float4 a0 = A0[v];
            acc0 += a0.x * x.x + a0.y * x.y + a0.z * x.z + a0.w * x.w;
            const float4 a1 = A1[v];
            acc1 += a1.x * x.x + a1.y * x.y + a1.z * x.z + a1.w * x.w;
        }
#pragma unroll
        for (int off = 16; off > 0; off >>= 1) {
            acc0 += __shfl_xor_sync(0xFFFFFFFFu, acc0, off);
            acc1 += __shfl_xor_sync(0xFFFFFFFFu, acc1, off);
        }
        if (lane == 0) {
            s_part[hf * 8 + pr * 2]     = acc0;
            s_part[hf * 8 + pr * 2 + 1] = acc1;
        }
        __syncthreads();

        if (tid < 8) {
            const int r = blockIdx.x * 8 + tid;
            const float z = s_part[tid] + s_part[8 + tid] + b_y[r];
            d_out[r] = 1.0f / (1.0f + expf(-z));   // "output" slice
        }
    } else {
        // Tiny tail block: 3 dot products over h (2 warps each, K halves),
        // softmax, stack blend.
        __shared__ float s_tail[6];
        __shared__ float s_sc[3];

        if (warp < 6) {
            const int trow = warp >> 1;          // 0,1: W_a rows; 2: W_n
            const int hf   = warp & 1;
            const int base = hf * 512;
            const float* __restrict__ Wrow =
                (trow < 2) ? (W_a + (size_t)trow * H) : W_n;
            const float4* __restrict__ A4 = (const float4*)Wrow;
            const float4* __restrict__ h4 = (const float4*)g_h;
            float acc = 0.0f;
#pragma unroll 8
            for (int k = 0; k < 16; ++k) {
                const int v = base + lane + k * 32;
                const float4 a = A4[v];
                const float4 x = h4[v];
                acc += a.x * x.x + a.y * x.y + a.z * x.z + a.w * x.w;
            }
#pragma unroll
            for (int off = 16; off > 0; off >>= 1)
                acc += __shfl_xor_sync(0xFFFFFFFFu, acc, off);
            if (lane == 0) s_tail[warp] = acc;
        }
        __syncthreads();

        if (tid == 0) {
            const float d0 = s_tail[0] + s_tail[1] + b_a[0];
            const float d1 = s_tail[2] + s_tail[3] + b_a[1];
            const float dn = s_tail[4] + s_tail[5] + b_n[0];
            const float m  = fmaxf(d0, d1);
            const float e0 = expf(d0 - m);
            const float e1 = expf(d1 - m);
            const float inv = 1.0f / (e0 + e1);
            s_sc[0] = e0 * inv;
            s_sc[1] = e1 * inv;
            s_sc[2] = 1.0f / (1.0f + expf(-dn));
            d_out[2 * H + M_STACK] = e0 * inv + e1 * inv;   // "weights"
        }
        __syncthreads();

        if (tid < M_STACK) {
            const float push = (tid == 0) ? s_sc[2] : stack[tid - 1];
            const float pop  = (tid < M_STACK - 1) ? stack[tid + 1] : 0.0f;
            d_out[2 * H + tid] = s_sc[0] * push + s_sc[1] * pop;  // "new_stack"
        }
    }
}

// ---------------------------------------------------------------------------
// Launch
// Inputs (metadata order): 0 inp(int), 1 hidden0, 2 stack, 3 E, 4 W_ih,
// 5 b_ih, 6 W_hh, 7 b_hh, 8 W_y, 9 b_y, 10 W_n, 11 b_n, 12 W_a, 13 b_a,
// 14 W_sh, 15 b_sh.
// Output layout: [output 4096 | hidden 4096 | new_stack 104 | weights 1]
// ---------------------------------------------------------------------------
extern "C" void kernel_launch(void* const* d_in, const int* in_sizes, int n_in,
                              void* d_out, int out_size)
{
    (void)in_sizes; (void)n_in; (void)out_size;

    const int*   inp     = (const int*)  d_in[0];
    const float* hidden0 = (const float*)d_in[1];
    const float* stack   = (const float*)d_in[2];
    const float* E       = (const float*)d_in[3];
    const float* W_ih    = (const float*)d_in[4];
    const float* b_ih    = (const float*)d_in[5];
    const float* W_hh    = (const float*)d_in[6];
    const float* b_hh    = (const float*)d_in[7];
    const float* W_y     = (const float*)d_in[8];
    const float* b_y     = (const float*)d_in[9];
    const float* W_n     = (const float*)d_in[10];
    const float* b_n     = (const float*)d_in[11];
    const float* W_a     = (const float*)d_in[12];
    const float* b_a     = (const float*)d_in[13];
    const float* W_sh    = (const float*)d_in[14];
    const float* b_sh    = (const float*)d_in[15];

    float* out = (float*)d_out;

    srnn_hidden_kernel<<<512, 256>>>(inp, hidden0, stack, E, W_ih, b_ih,
                                     W_hh, b_hh, W_sh, b_sh, out + H);
    srnn_output_kernel<<<513, 256>>>(W_y, b_y, W_n, b_n, W_a, b_a,
                                     stack, out);
}